// round 7
// baseline (speedup 1.0000x reference)
#include <cuda_runtime.h>
#include <math.h>
#include <stdint.h>

#define NNODE 50000
#define NEDGE 800000
#define ND    128
#define NH    8
#define DKK   16
#define FFD   512

// ---------------- scratch ----------------
__device__ float g_q [NNODE * ND];
__device__ float g_k [NNODE * ND];
__device__ float g_v [NNODE * ND];
__device__ float g_wv[NNODE * ND];
__device__ float g_t1[NNODE * ND];
__device__ float g_ff[NNODE * FFD];
__device__ float g_x1[NNODE * ND];

// CSR scratch
__device__ int  g_deg[NNODE];
__device__ int  g_off[NNODE + 1];
__device__ int2 g_pe [NEDGE];        // (src, rel) in dst-grouped order

// ---------------- mma helper (raw fp32 bits; HW truncates to tf32) ----------------
__device__ __forceinline__ void mma_tf32(float* c, const uint32_t* a, const uint32_t* b) {
    asm volatile(
        "mma.sync.aligned.m16n8k8.row.col.f32.tf32.tf32.f32 "
        "{%0,%1,%2,%3}, {%4,%5,%6,%7}, {%8,%9}, {%0,%1,%2,%3};"
        : "+f"(c[0]), "+f"(c[1]), "+f"(c[2]), "+f"(c[3])
        : "r"(a[0]), "r"(a[1]), "r"(a[2]), "r"(a[3]),
          "r"(b[0]), "r"(b[1]));
}

__device__ __forceinline__ void cp16(float* dst, const float* src, bool pred) {
    uint32_t d = (uint32_t)__cvta_generic_to_shared(dst);
    int sz = pred ? 16 : 0;
    asm volatile("cp.async.cg.shared.global [%0], [%1], 16, %2;"
                 :: "r"(d), "l"(src), "r"(sz));
}

// ---------------- TF32 GEMM core: 3-stage pipeline, 1 barrier/stage ----------------
#define KC 32
#define SK 36
#define SN 132
#define TILE (128 * SK)
#define NSTAGE 3
#define GEMM_SMEM_BYTES (NSTAGE * 2 * TILE * 4)   // 110592 B; epilogue needs 67584 <= this

template<bool RELU, bool LN>
__device__ __forceinline__ void gemm_body(
    const float* __restrict__ X, const float* __restrict__ W,
    const float* bias, const float* res,
    const float* gam, const float* bet,
    float* __restrict__ C, int M, int K, int NOUT, int bm, int bn)
{
    extern __shared__ float smem[];

    const int tid  = threadIdx.x;
    const int lane = tid & 31;
    const int wid  = tid >> 5;
    const int g    = lane >> 2;
    const int tig  = lane & 3;
    const int wn   = (wid & 3) * 32;
    const int wm   = (wid >> 2) * 64;

    float c[2][8][4];
#pragma unroll
    for (int i = 0; i < 2; i++)
#pragma unroll
        for (int j = 0; j < 8; j++)
#pragma unroll
            for (int t = 0; t < 4; t++) c[i][j][t] = 0.f;

    const int nsteps = K / KC;

    auto prefetch = [&](int s, int b) {
        float* Wb = smem + b * 2 * TILE;
        float* Xb = Wb + TILE;
        int k0 = s * KC;
#pragma unroll
        for (int i = 0; i < 4; i++) {
            int idx = tid + i * 256;
            int r = idx >> 3, cq = idx & 7;
            cp16(&Wb[r * SK + cq * 4], &W[(long)(bn + r) * K + k0 + cq * 4], true);
        }
#pragma unroll
        for (int i = 0; i < 4; i++) {
            int idx = tid + i * 256;
            int r = idx >> 3, cq = idx & 7;
            int gm = bm + r;
            cp16(&Xb[r * SK + cq * 4], &X[(long)gm * K + k0 + cq * 4], gm < M);
        }
        asm volatile("cp.async.commit_group;" ::: "memory");
    };

    prefetch(0, 0);
    if (nsteps > 1) prefetch(1, 1);

    int buf = 0;
    for (int s = 0; s < nsteps; s++) {
        if (s + 1 < nsteps) asm volatile("cp.async.wait_group 1;" ::: "memory");
        else                asm volatile("cp.async.wait_group 0;" ::: "memory");
        __syncthreads();
        // prefetch s+2 into the buffer freed by stage s-1 (drained at barrier above)
        if (s + 2 < nsteps) {
            int nb = buf + 2; if (nb >= NSTAGE) nb -= NSTAGE;
            prefetch(s + 2, nb);
        }

        const uint32_t* Wsu = (const uint32_t*)(smem + buf * 2 * TILE);
        const uint32_t* Xsu = Wsu + TILE;

#pragma unroll
        for (int ks = 0; ks < KC / 8; ks++) {
            const int kk = ks * 8;
            uint32_t a[2][4];
#pragma unroll
            for (int tn = 0; tn < 2; tn++) {
                int row = wn + tn * 16 + g;
                a[tn][0] = Wsu[row * SK + kk + tig];
                a[tn][1] = Wsu[(row + 8) * SK + kk + tig];
                a[tn][2] = Wsu[row * SK + kk + tig + 4];
                a[tn][3] = Wsu[(row + 8) * SK + kk + tig + 4];
            }
            uint32_t b[8][2];
#pragma unroll
            for (int tm = 0; tm < 8; tm++) {
                int col = wm + tm * 8 + g;
                b[tm][0] = Xsu[col * SK + kk + tig];
                b[tm][1] = Xsu[col * SK + kk + tig + 4];
            }
#pragma unroll
            for (int tn = 0; tn < 2; tn++)
#pragma unroll
                for (int tm = 0; tm < 8; tm++)
                    mma_tf32(c[tn][tm], a[tn], b[tm]);
        }
        if (++buf == NSTAGE) buf = 0;
    }
    __syncthreads();   // last compute buffer drained before smem reuse as Cs

    float* Cs = smem;
#pragma unroll
    for (int tn = 0; tn < 2; tn++)
#pragma unroll
        for (int tm = 0; tm < 8; tm++) {
            int n = wn + tn * 16 + g;
            int m = wm + tm * 8 + tig * 2;
            Cs[m * SN + n]           = c[tn][tm][0];
            Cs[(m + 1) * SN + n]     = c[tn][tm][1];
            Cs[m * SN + n + 8]       = c[tn][tm][2];
            Cs[(m + 1) * SN + n + 8] = c[tn][tm][3];
        }
    __syncthreads();

#pragma unroll
    for (int i = 0; i < 16; i++) {
        int idx = tid + i * 256;
        int mm = idx >> 5, nq = idx & 31;
        int gm = bm + mm;
        if (gm >= M) continue;
        float4 cv = *(float4*)&Cs[mm * SN + nq * 4];
        if (bias) {
            float4 b4 = *(const float4*)&bias[bn + nq * 4];
            cv.x += b4.x; cv.y += b4.y; cv.z += b4.z; cv.w += b4.w;
        }
        if (res) {
            float4 r4 = *(const float4*)&res[(long)gm * NOUT + bn + nq * 4];
            cv.x += r4.x; cv.y += r4.y; cv.z += r4.z; cv.w += r4.w;
        }
        if (RELU) {
            cv.x = fmaxf(cv.x, 0.f); cv.y = fmaxf(cv.y, 0.f);
            cv.z = fmaxf(cv.z, 0.f); cv.w = fmaxf(cv.w, 0.f);
        }
        if (LN) {
            float s4 = cv.x + cv.y + cv.z + cv.w;
#pragma unroll
            for (int o = 16; o; o >>= 1) s4 += __shfl_xor_sync(0xffffffffu, s4, o);
            float mean = s4 * (1.f / 128.f);
            float dx = cv.x - mean, dy = cv.y - mean, dz = cv.z - mean, dw = cv.w - mean;
            float vv = dx * dx + dy * dy + dz * dz + dw * dw;
#pragma unroll
            for (int o = 16; o; o >>= 1) vv += __shfl_xor_sync(0xffffffffu, vv, o);
            float inv = rsqrtf(vv * (1.f / 128.f) + 1e-5f);
            float4 g4 = *(const float4*)&gam[nq * 4];
            float4 b4 = *(const float4*)&bet[nq * 4];
            cv.x = dx * inv * g4.x + b4.x;
            cv.y = dy * inv * g4.y + b4.y;
            cv.z = dz * inv * g4.z + b4.z;
            cv.w = dw * inv * g4.w + b4.w;
        }
        *(float4*)&C[(long)gm * NOUT + bn + nq * 4] = cv;
    }
}

template<bool RELU, bool LN>
__global__ __launch_bounds__(256, 2) void gemm_k(
    const float* __restrict__ X, const float* __restrict__ W,
    const float* bias, const float* res,
    const float* gam, const float* bet,
    float* __restrict__ C, int M, int K, int NOUT)
{
    gemm_body<RELU, LN>(X, W, bias, res, gam, bet, C, M, K, NOUT,
                        blockIdx.x * 128, blockIdx.y * 128);
}

__global__ __launch_bounds__(256, 2) void qkv_k(
    const float* __restrict__ X,
    const float* __restrict__ Wq, const float* __restrict__ Wk,
    const float* __restrict__ Wv, const float* __restrict__ bq,
    float* __restrict__ q, float* __restrict__ k, float* __restrict__ v, int M)
{
    int w = blockIdx.y;
    const float* W = (w == 0) ? Wq : (w == 1) ? Wk : Wv;
    const float* bias = (w == 0) ? bq : nullptr;
    float* C = (w == 0) ? q : (w == 1) ? k : v;
    gemm_body<false, false>(X, W, bias, nullptr, nullptr, nullptr, C, M, ND, ND,
                            blockIdx.x * 128, 0);
}

// ================= CSR build =================
__global__ void hist_kernel(const int* __restrict__ dst)
{
    int e = blockIdx.x * blockDim.x + threadIdx.x;
    if (e < NEDGE) atomicAdd(&g_deg[dst[e]], 1);
}

__global__ void scan_kernel()
{
    __shared__ int sh[1024];
    __shared__ int carry;
    int t = threadIdx.x;
    if (t == 0) { carry = 0; g_off[0] = 0; }
    __syncthreads();
    for (int base = 0; base < NNODE; base += 1024) {
        int i = base + t;
        int val = (i < NNODE) ? g_deg[i] : 0;
        sh[t] = val;
        __syncthreads();
#pragma unroll
        for (int o = 1; o < 1024; o <<= 1) {
            int add = (t >= o) ? sh[t - o] : 0;
            __syncthreads();
            sh[t] += add;
            __syncthreads();
        }
        int inc = sh[t] + carry;
        if (i < NNODE) g_off[i + 1] = inc;
        __syncthreads();
        if (t == 1023) carry = inc;
        __syncthreads();
    }
}

__global__ void scatter_kernel(const int* __restrict__ src,
                               const int* __restrict__ dst,
                               const int* __restrict__ edges)
{
    int e = blockIdx.x * blockDim.x + threadIdx.x;
    if (e >= NEDGE) return;
    int d = dst[e];
    int idx = atomicAdd(&g_deg[d], -1) - 1;
    g_pe[g_off[d] + idx] = make_int2(src[e], edges[e]);
}

// ================= per-dst aggregation (one warp per node, 4-wide MLP) =================
__global__ __launch_bounds__(256) void agg_kernel(const float* __restrict__ rel)
{
    int node = (blockIdx.x * blockDim.x + threadIdx.x) >> 5;
    int lane = threadIdx.x & 31;
    if (node >= NNODE) return;

    const int beg = g_off[node];
    const int end = g_off[node + 1];

    const float4 q4 = *(const float4*)&g_q[(long)node * ND + lane * 4];
    float4 acc = make_float4(0.f, 0.f, 0.f, 0.f);
    float zacc = 0.f;

    int i = beg;
    for (; i + 4 <= end; i += 4) {
        int2 p[4];
        p[0] = g_pe[i]; p[1] = g_pe[i + 1]; p[2] = g_pe[i + 2]; p[3] = g_pe[i + 3];
        float4 e[4], kk[4], vv[4];
#pragma unroll
        for (int j = 0; j < 4; j++) {
            e[j]  = *(const float4*)&rel[(long)p[j].y * DKK + (lane & 3) * 4];
            kk[j] = *(const float4*)&g_k[(long)p[j].x * ND + lane * 4];
            vv[j] = *(const float4*)&g_v[(long)p[j].x * ND + lane * 4];
        }
        float s[4];
#pragma unroll
        for (int j = 0; j < 4; j++)
            s[j] = (kk[j].x + e[j].x) * q4.x + (kk[j].y + e[j].y) * q4.y +
                   (kk[j].z + e[j].z) * q4.z + (kk[j].w + e[j].w) * q4.w;
#pragma unroll
        for (int j = 0; j < 4; j++) {
            s[j] += __shfl_xor_sync(0xffffffffu, s[j], 1);
            s[j] += __shfl_xor_sync(0xffffffffu, s[j], 2);
        }
#pragma unroll
        for (int j = 0; j < 4; j++) {
            float sc = __expf(fminf(fmaxf(s[j] * 0.25f, -5.f), 5.f));
            acc.x += (vv[j].x + e[j].x) * sc;
            acc.y += (vv[j].y + e[j].y) * sc;
            acc.z += (vv[j].z + e[j].z) * sc;
            acc.w += (vv[j].w + e[j].w) * sc;
            zacc  += sc;
        }
    }
    for (; i < end; i++) {
        int2 p0 = g_pe[i];
        const float4 e0 = *(const float4*)&rel[(long)p0.y * DKK + (lane & 3) * 4];
        const float4 k0 = *(const float4*)&g_k[(long)p0.x * ND + lane * 4];
        const float4 v0 = *(const float4*)&g_v[(long)p0.x * ND + lane * 4];
        float s0 = (k0.x + e0.x) * q4.x + (k0.y + e0.y) * q4.y +
                   (k0.z + e0.z) * q4.z + (k0.w + e0.w) * q4.w;
        s0 += __shfl_xor_sync(0xffffffffu, s0, 1);
        s0 += __shfl_xor_sync(0xffffffffu, s0, 2);
        float sc0 = __expf(fminf(fmaxf(s0 * 0.25f, -5.f), 5.f));
        acc.x += (v0.x + e0.x) * sc0;
        acc.y += (v0.y + e0.y) * sc0;
        acc.z += (v0.z + e0.z) * sc0;
        acc.w += (v0.w + e0.w) * sc0;
        zacc  += sc0;
    }

    float inv = 1.f / zacc;
    float4 o;
    o.x = acc.x * inv; o.y = acc.y * inv; o.z = acc.z * inv; o.w = acc.w * inv;
    *(float4*)&g_wv[(long)node * ND + lane * 4] = o;
}

// ---------------- host driver ----------------
extern "C" void kernel_launch(void* const* d_in, const int* in_sizes, int n_in,
                              void* d_out, int out_size)
{
    const float* x     = (const float*)d_in[0];
    const int*   edges = (const int*)  d_in[1];
    const int*   src   = (const int*)  d_in[2];
    const int*   dst   = (const int*)  d_in[3];
    const float* rel   = (const float*)d_in[4];
    const float* Wq    = (const float*)d_in[5];
    const float* bq    = (const float*)d_in[6];
    const float* Wk    = (const float*)d_in[7];
    const float* Wv    = (const float*)d_in[8];
    const float* Wo    = (const float*)d_in[9];
    const float* bo    = (const float*)d_in[10];
    const float* ln1g  = (const float*)d_in[11];
    const float* ln1b  = (const float*)d_in[12];
    const float* W1    = (const float*)d_in[13];
    const float* b1    = (const float*)d_in[14];
    const float* W2    = (const float*)d_in[15];
    const float* b2    = (const float*)d_in[16];
    const float* ln2g  = (const float*)d_in[17];
    const float* ln2b  = (const float*)d_in[18];

    const int M = NNODE;
    const int E = NEDGE;

    float *q, *k, *v, *wv, *t1, *ff, *x1;
    int* degp;
    cudaGetSymbolAddress((void**)&q,  g_q);
    cudaGetSymbolAddress((void**)&k,  g_k);
    cudaGetSymbolAddress((void**)&v,  g_v);
    cudaGetSymbolAddress((void**)&wv, g_wv);
    cudaGetSymbolAddress((void**)&t1, g_t1);
    cudaGetSymbolAddress((void**)&ff, g_ff);
    cudaGetSymbolAddress((void**)&x1, g_x1);
    cudaGetSymbolAddress((void**)&degp, g_deg);

    cudaFuncSetAttribute(gemm_k<false, true>,
        cudaFuncAttributeMaxDynamicSharedMemorySize, GEMM_SMEM_BYTES);
    cudaFuncSetAttribute(gemm_k<true, false>,
        cudaFuncAttributeMaxDynamicSharedMemorySize, GEMM_SMEM_BYTES);
    cudaFuncSetAttribute(qkv_k,
        cudaFuncAttributeMaxDynamicSharedMemorySize, GEMM_SMEM_BYTES);

    const int MB = (M + 127) / 128;
    dim3 gQKV(MB, 3);
    dim3 gP(MB, 1);
    dim3 gF1(MB, FFD / 128);
    int eBlocks   = (E + 255) / 256;
    int aggBlocks = (M * 32 + 255) / 256;

    // ---- CSR build (graph is call-constant; build once) ----
    cudaMemsetAsync(degp, 0, NNODE * sizeof(int));
    hist_kernel<<<eBlocks, 256>>>(dst);
    scan_kernel<<<1, 1024>>>();
    scatter_kernel<<<eBlocks, 256>>>(src, dst, edges);

    const float* xin = x;
    for (int li = 0; li < 2; li++) {
        float* xout = (li == 0) ? x1 : (float*)d_out;
        const float* wWq = Wq + (long)li * ND * ND;
        const float* wWk = Wk + (long)li * ND * ND;
        const float* wWv = Wv + (long)li * ND * ND;
        const float* wWo = Wo + (long)li * ND * ND;
        const float* wW1 = W1 + (long)li * FFD * ND;
        const float* wW2 = W2 + (long)li * ND * FFD;

        qkv_k<<<gQKV, 256, GEMM_SMEM_BYTES>>>(xin, wWq, wWk, wWv, bq + li * ND, q, k, v, M);

        agg_kernel<<<aggBlocks, 256>>>(rel);

        gemm_k<false, true><<<gP, 256, GEMM_SMEM_BYTES>>>(
            wv, wWo, bo + li * ND, xin, ln1g + li * ND, ln1b + li * ND, t1, M, ND, ND);

        gemm_k<true, false><<<gF1, 256, GEMM_SMEM_BYTES>>>(
            t1, wW1, b1 + li * FFD, nullptr, nullptr, nullptr, ff, M, ND, FFD);

        gemm_k<false, true><<<gP, 256, GEMM_SMEM_BYTES>>>(
            ff, wW2, b2 + li * ND, t1, ln2g + li * ND, ln2b + li * ND, xout, M, FFD, ND);

        xin = xout;
    }
}

// round 8
// speedup vs baseline: 1.0370x; 1.0370x over previous
#include <cuda_runtime.h>
#include <math.h>
#include <stdint.h>

#define NNODE 50000
#define NEDGE 800000
#define ND    128
#define NH    8
#define DKK   16
#define FFD   512

// ---------------- scratch ----------------
__device__ float g_q [NNODE * ND];
__device__ float g_k [NNODE * ND];
__device__ float g_v [NNODE * ND];
__device__ float g_wv[NNODE * ND];
__device__ float g_t1[NNODE * ND];
__device__ float g_ff[NNODE * FFD];
__device__ float g_x1[NNODE * ND];

// CSR scratch
__device__ int  g_deg[NNODE];
__device__ int  g_off[NNODE + 1];
__device__ int2 g_pe [NEDGE];        // (src, rel) in dst-grouped order

// ---------------- mma helper (raw fp32 bits; HW truncates to tf32) ----------------
__device__ __forceinline__ void mma_tf32(float* c, const uint32_t* a, const uint32_t* b) {
    asm volatile(
        "mma.sync.aligned.m16n8k8.row.col.f32.tf32.tf32.f32 "
        "{%0,%1,%2,%3}, {%4,%5,%6,%7}, {%8,%9}, {%0,%1,%2,%3};"
        : "+f"(c[0]), "+f"(c[1]), "+f"(c[2]), "+f"(c[3])
        : "r"(a[0]), "r"(a[1]), "r"(a[2]), "r"(a[3]),
          "r"(b[0]), "r"(b[1]));
}

__device__ __forceinline__ void cp16(float* dst, const float* src, bool pred) {
    uint32_t d = (uint32_t)__cvta_generic_to_shared(dst);
    int sz = pred ? 16 : 0;
    asm volatile("cp.async.cg.shared.global [%0], [%1], 16, %2;"
                 :: "r"(d), "l"(src), "r"(sz));
}

// ---------------- TF32 GEMM core: 3-stage pipeline, 1 barrier/stage ----------------
#define KC 32
#define SK 36
#define SN 132
#define TILE (128 * SK)
#define NSTAGE 3
#define GEMM_SMEM_BYTES (NSTAGE * 2 * TILE * 4)   // 110592 B; epilogue needs 67584 <= this

template<bool RELU, bool LN>
__device__ __forceinline__ void gemm_body(
    const float* __restrict__ X, const float* __restrict__ W,
    const float* bias, const float* res,
    const float* gam, const float* bet,
    float* __restrict__ C, int M, int K, int NOUT, int bm, int bn)
{
    extern __shared__ float smem[];

    const int tid  = threadIdx.x;
    const int lane = tid & 31;
    const int wid  = tid >> 5;
    const int g    = lane >> 2;
    const int tig  = lane & 3;
    const int wn   = (wid & 3) * 32;
    const int wm   = (wid >> 2) * 64;

    float c[2][8][4];
#pragma unroll
    for (int i = 0; i < 2; i++)
#pragma unroll
        for (int j = 0; j < 8; j++)
#pragma unroll
            for (int t = 0; t < 4; t++) c[i][j][t] = 0.f;

    const int nsteps = K / KC;

    auto prefetch = [&](int s, int b) {
        float* Wb = smem + b * 2 * TILE;
        float* Xb = Wb + TILE;
        int k0 = s * KC;
#pragma unroll
        for (int i = 0; i < 4; i++) {
            int idx = tid + i * 256;
            int r = idx >> 3, cq = idx & 7;
            cp16(&Wb[r * SK + cq * 4], &W[(long)(bn + r) * K + k0 + cq * 4], true);
        }
#pragma unroll
        for (int i = 0; i < 4; i++) {
            int idx = tid + i * 256;
            int r = idx >> 3, cq = idx & 7;
            int gm = bm + r;
            cp16(&Xb[r * SK + cq * 4], &X[(long)gm * K + k0 + cq * 4], gm < M);
        }
        asm volatile("cp.async.commit_group;" ::: "memory");
    };

    prefetch(0, 0);
    if (nsteps > 1) prefetch(1, 1);

    int buf = 0;
    for (int s = 0; s < nsteps; s++) {
        if (s + 1 < nsteps) asm volatile("cp.async.wait_group 1;" ::: "memory");
        else                asm volatile("cp.async.wait_group 0;" ::: "memory");
        __syncthreads();
        // prefetch s+2 into the buffer freed by stage s-1 (drained at barrier above)
        if (s + 2 < nsteps) {
            int nb = buf + 2; if (nb >= NSTAGE) nb -= NSTAGE;
            prefetch(s + 2, nb);
        }

        const uint32_t* Wsu = (const uint32_t*)(smem + buf * 2 * TILE);
        const uint32_t* Xsu = Wsu + TILE;

#pragma unroll
        for (int ks = 0; ks < KC / 8; ks++) {
            const int kk = ks * 8;
            uint32_t a[2][4];
#pragma unroll
            for (int tn = 0; tn < 2; tn++) {
                int row = wn + tn * 16 + g;
                a[tn][0] = Wsu[row * SK + kk + tig];
                a[tn][1] = Wsu[(row + 8) * SK + kk + tig];
                a[tn][2] = Wsu[row * SK + kk + tig + 4];
                a[tn][3] = Wsu[(row + 8) * SK + kk + tig + 4];
            }
            uint32_t b[8][2];
#pragma unroll
            for (int tm = 0; tm < 8; tm++) {
                int col = wm + tm * 8 + g;
                b[tm][0] = Xsu[col * SK + kk + tig];
                b[tm][1] = Xsu[col * SK + kk + tig + 4];
            }
#pragma unroll
            for (int tn = 0; tn < 2; tn++)
#pragma unroll
                for (int tm = 0; tm < 8; tm++)
                    mma_tf32(c[tn][tm], a[tn], b[tm]);
        }
        if (++buf == NSTAGE) buf = 0;
    }
    __syncthreads();   // last compute buffer drained before smem reuse as Cs

    float* Cs = smem;
#pragma unroll
    for (int tn = 0; tn < 2; tn++)
#pragma unroll
        for (int tm = 0; tm < 8; tm++) {
            int n = wn + tn * 16 + g;
            int m = wm + tm * 8 + tig * 2;
            Cs[m * SN + n]           = c[tn][tm][0];
            Cs[(m + 1) * SN + n]     = c[tn][tm][1];
            Cs[m * SN + n + 8]       = c[tn][tm][2];
            Cs[(m + 1) * SN + n + 8] = c[tn][tm][3];
        }
    __syncthreads();

#pragma unroll
    for (int i = 0; i < 16; i++) {
        int idx = tid + i * 256;
        int mm = idx >> 5, nq = idx & 31;
        int gm = bm + mm;
        if (gm >= M) continue;
        float4 cv = *(float4*)&Cs[mm * SN + nq * 4];
        if (bias) {
            float4 b4 = *(const float4*)&bias[bn + nq * 4];
            cv.x += b4.x; cv.y += b4.y; cv.z += b4.z; cv.w += b4.w;
        }
        if (res) {
            float4 r4 = *(const float4*)&res[(long)gm * NOUT + bn + nq * 4];
            cv.x += r4.x; cv.y += r4.y; cv.z += r4.z; cv.w += r4.w;
        }
        if (RELU) {
            cv.x = fmaxf(cv.x, 0.f); cv.y = fmaxf(cv.y, 0.f);
            cv.z = fmaxf(cv.z, 0.f); cv.w = fmaxf(cv.w, 0.f);
        }
        if (LN) {
            float s4 = cv.x + cv.y + cv.z + cv.w;
#pragma unroll
            for (int o = 16; o; o >>= 1) s4 += __shfl_xor_sync(0xffffffffu, s4, o);
            float mean = s4 * (1.f / 128.f);
            float dx = cv.x - mean, dy = cv.y - mean, dz = cv.z - mean, dw = cv.w - mean;
            float vv = dx * dx + dy * dy + dz * dz + dw * dw;
#pragma unroll
            for (int o = 16; o; o >>= 1) vv += __shfl_xor_sync(0xffffffffu, vv, o);
            float inv = rsqrtf(vv * (1.f / 128.f) + 1e-5f);
            float4 g4 = *(const float4*)&gam[nq * 4];
            float4 b4 = *(const float4*)&bet[nq * 4];
            cv.x = dx * inv * g4.x + b4.x;
            cv.y = dy * inv * g4.y + b4.y;
            cv.z = dz * inv * g4.z + b4.z;
            cv.w = dw * inv * g4.w + b4.w;
        }
        *(float4*)&C[(long)gm * NOUT + bn + nq * 4] = cv;
    }
}

template<bool RELU, bool LN>
__global__ __launch_bounds__(256, 2) void gemm_k(
    const float* __restrict__ X, const float* __restrict__ W,
    const float* bias, const float* res,
    const float* gam, const float* bet,
    float* __restrict__ C, int M, int K, int NOUT)
{
    gemm_body<RELU, LN>(X, W, bias, res, gam, bet, C, M, K, NOUT,
                        blockIdx.x * 128, blockIdx.y * 128);
}

__global__ __launch_bounds__(256, 2) void qkv_k(
    const float* __restrict__ X,
    const float* __restrict__ Wq, const float* __restrict__ Wk,
    const float* __restrict__ Wv, const float* __restrict__ bq,
    float* __restrict__ q, float* __restrict__ k, float* __restrict__ v, int M)
{
    int w = blockIdx.y;
    const float* W = (w == 0) ? Wq : (w == 1) ? Wk : Wv;
    const float* bias = (w == 0) ? bq : nullptr;
    float* C = (w == 0) ? q : (w == 1) ? k : v;
    gemm_body<false, false>(X, W, bias, nullptr, nullptr, nullptr, C, M, ND, ND,
                            blockIdx.x * 128, 0);
}

// ================= CSR build =================
__global__ void hist_kernel(const int* __restrict__ dst)
{
    int e = blockIdx.x * blockDim.x + threadIdx.x;
    if (e < NEDGE) atomicAdd(&g_deg[dst[e]], 1);
}

__global__ void scan_kernel()
{
    __shared__ int sh[1024];
    __shared__ int carry;
    int t = threadIdx.x;
    if (t == 0) { carry = 0; g_off[0] = 0; }
    __syncthreads();
    for (int base = 0; base < NNODE; base += 1024) {
        int i = base + t;
        int val = (i < NNODE) ? g_deg[i] : 0;
        sh[t] = val;
        __syncthreads();
#pragma unroll
        for (int o = 1; o < 1024; o <<= 1) {
            int add = (t >= o) ? sh[t - o] : 0;
            __syncthreads();
            sh[t] += add;
            __syncthreads();
        }
        int inc = sh[t] + carry;
        if (i < NNODE) g_off[i + 1] = inc;
        __syncthreads();
        if (t == 1023) carry = inc;
        __syncthreads();
    }
}

__global__ void scatter_kernel(const int* __restrict__ src,
                               const int* __restrict__ dst,
                               const int* __restrict__ edges)
{
    int e = blockIdx.x * blockDim.x + threadIdx.x;
    if (e >= NEDGE) return;
    int d = dst[e];
    int idx = atomicAdd(&g_deg[d], -1) - 1;
    g_pe[g_off[d] + idx] = make_int2(src[e], edges[e]);
}

// ================= per-dst aggregation (one warp per node, 2-wide) =================
__global__ __launch_bounds__(256) void agg_kernel(const float* __restrict__ rel)
{
    int node = (blockIdx.x * blockDim.x + threadIdx.x) >> 5;
    int lane = threadIdx.x & 31;
    if (node >= NNODE) return;

    const int beg = g_off[node];
    const int end = g_off[node + 1];

    const float4 q4 = *(const float4*)&g_q[(long)node * ND + lane * 4];
    float4 acc = make_float4(0.f, 0.f, 0.f, 0.f);
    float zacc = 0.f;

    int i = beg;
    for (; i + 2 <= end; i += 2) {
        int2 p0 = g_pe[i];
        int2 p1 = g_pe[i + 1];
        const float4 e0 = *(const float4*)&rel[(long)p0.y * DKK + (lane & 3) * 4];
        const float4 e1 = *(const float4*)&rel[(long)p1.y * DKK + (lane & 3) * 4];
        const float4 k0 = *(const float4*)&g_k[(long)p0.x * ND + lane * 4];
        const float4 k1 = *(const float4*)&g_k[(long)p1.x * ND + lane * 4];
        const float4 v0 = *(const float4*)&g_v[(long)p0.x * ND + lane * 4];
        const float4 v1 = *(const float4*)&g_v[(long)p1.x * ND + lane * 4];

        float s0 = (k0.x + e0.x) * q4.x + (k0.y + e0.y) * q4.y +
                   (k0.z + e0.z) * q4.z + (k0.w + e0.w) * q4.w;
        float s1 = (k1.x + e1.x) * q4.x + (k1.y + e1.y) * q4.y +
                   (k1.z + e1.z) * q4.z + (k1.w + e1.w) * q4.w;
        s0 += __shfl_xor_sync(0xffffffffu, s0, 1);
        s1 += __shfl_xor_sync(0xffffffffu, s1, 1);
        s0 += __shfl_xor_sync(0xffffffffu, s0, 2);
        s1 += __shfl_xor_sync(0xffffffffu, s1, 2);

        float sc0 = __expf(fminf(fmaxf(s0 * 0.25f, -5.f), 5.f));
        float sc1 = __expf(fminf(fmaxf(s1 * 0.25f, -5.f), 5.f));

        acc.x += (v0.x + e0.x) * sc0 + (v1.x + e1.x) * sc1;
        acc.y += (v0.y + e0.y) * sc0 + (v1.y + e1.y) * sc1;
        acc.z += (v0.z + e0.z) * sc0 + (v1.z + e1.z) * sc1;
        acc.w += (v0.w + e0.w) * sc0 + (v1.w + e1.w) * sc1;
        zacc  += sc0 + sc1;
    }
    if (i < end) {
        int2 p0 = g_pe[i];
        const float4 e0 = *(const float4*)&rel[(long)p0.y * DKK + (lane & 3) * 4];
        const float4 k0 = *(const float4*)&g_k[(long)p0.x * ND + lane * 4];
        const float4 v0 = *(const float4*)&g_v[(long)p0.x * ND + lane * 4];
        float s0 = (k0.x + e0.x) * q4.x + (k0.y + e0.y) * q4.y +
                   (k0.z + e0.z) * q4.z + (k0.w + e0.w) * q4.w;
        s0 += __shfl_xor_sync(0xffffffffu, s0, 1);
        s0 += __shfl_xor_sync(0xffffffffu, s0, 2);
        float sc0 = __expf(fminf(fmaxf(s0 * 0.25f, -5.f), 5.f));
        acc.x += (v0.x + e0.x) * sc0;
        acc.y += (v0.y + e0.y) * sc0;
        acc.z += (v0.z + e0.z) * sc0;
        acc.w += (v0.w + e0.w) * sc0;
        zacc  += sc0;
    }

    float inv = 1.f / zacc;
    float4 o;
    o.x = acc.x * inv; o.y = acc.y * inv; o.z = acc.z * inv; o.w = acc.w * inv;
    *(float4*)&g_wv[(long)node * ND + lane * 4] = o;
}

// ---------------- host driver ----------------
extern "C" void kernel_launch(void* const* d_in, const int* in_sizes, int n_in,
                              void* d_out, int out_size)
{
    const float* x     = (const float*)d_in[0];
    const int*   edges = (const int*)  d_in[1];
    const int*   src   = (const int*)  d_in[2];
    const int*   dst   = (const int*)  d_in[3];
    const float* rel   = (const float*)d_in[4];
    const float* Wq    = (const float*)d_in[5];
    const float* bq    = (const float*)d_in[6];
    const float* Wk    = (const float*)d_in[7];
    const float* Wv    = (const float*)d_in[8];
    const float* Wo    = (const float*)d_in[9];
    const float* bo    = (const float*)d_in[10];
    const float* ln1g  = (const float*)d_in[11];
    const float* ln1b  = (const float*)d_in[12];
    const float* W1    = (const float*)d_in[13];
    const float* b1    = (const float*)d_in[14];
    const float* W2    = (const float*)d_in[15];
    const float* b2    = (const float*)d_in[16];
    const float* ln2g  = (const float*)d_in[17];
    const float* ln2b  = (const float*)d_in[18];

    const int M = NNODE;
    const int E = NEDGE;

    float *q, *k, *v, *wv, *t1, *ff, *x1;
    int* degp;
    cudaGetSymbolAddress((void**)&q,  g_q);
    cudaGetSymbolAddress((void**)&k,  g_k);
    cudaGetSymbolAddress((void**)&v,  g_v);
    cudaGetSymbolAddress((void**)&wv, g_wv);
    cudaGetSymbolAddress((void**)&t1, g_t1);
    cudaGetSymbolAddress((void**)&ff, g_ff);
    cudaGetSymbolAddress((void**)&x1, g_x1);
    cudaGetSymbolAddress((void**)&degp, g_deg);

    cudaFuncSetAttribute(gemm_k<false, true>,
        cudaFuncAttributeMaxDynamicSharedMemorySize, GEMM_SMEM_BYTES);
    cudaFuncSetAttribute(gemm_k<true, false>,
        cudaFuncAttributeMaxDynamicSharedMemorySize, GEMM_SMEM_BYTES);
    cudaFuncSetAttribute(qkv_k,
        cudaFuncAttributeMaxDynamicSharedMemorySize, GEMM_SMEM_BYTES);

    const int MB = (M + 127) / 128;
    dim3 gQKV(MB, 3);
    dim3 gP(MB, 1);
    dim3 gF1(MB, FFD / 128);
    int eBlocks   = (E + 255) / 256;
    int aggBlocks = (M * 32 + 255) / 256;

    // ---- CSR build (graph is call-constant; build once) ----
    cudaMemsetAsync(degp, 0, NNODE * sizeof(int));
    hist_kernel<<<eBlocks, 256>>>(dst);
    scan_kernel<<<1, 1024>>>();
    scatter_kernel<<<eBlocks, 256>>>(src, dst, edges);

    const float* xin = x;
    for (int li = 0; li < 2; li++) {
        float* xout = (li == 0) ? x1 : (float*)d_out;
        const float* wWq = Wq + (long)li * ND * ND;
        const float* wWk = Wk + (long)li * ND * ND;
        const float* wWv = Wv + (long)li * ND * ND;
        const float* wWo = Wo + (long)li * ND * ND;
        const float* wW1 = W1 + (long)li * FFD * ND;
        const float* wW2 = W2 + (long)li * ND * FFD;

        qkv_k<<<gQKV, 256, GEMM_SMEM_BYTES>>>(xin, wWq, wWk, wWv, bq + li * ND, q, k, v, M);

        agg_kernel<<<aggBlocks, 256>>>(rel);

        gemm_k<false, true><<<gP, 256, GEMM_SMEM_BYTES>>>(
            wv, wWo, bo + li * ND, xin, ln1g + li * ND, ln1b + li * ND, t1, M, ND, ND);

        gemm_k<true, false><<<gF1, 256, GEMM_SMEM_BYTES>>>(
            t1, wW1, b1 + li * FFD, nullptr, nullptr, nullptr, ff, M, ND, FFD);

        gemm_k<false, true><<<gP, 256, GEMM_SMEM_BYTES>>>(
            ff, wW2, b2 + li * ND, t1, ln2g + li * ND, ln2b + li * ND, xout, M, FFD, ND);

        xin = xout;
    }
}

// round 10
// speedup vs baseline: 1.1969x; 1.1542x over previous
#include <cuda_runtime.h>
#include <cuda_fp16.h>
#include <math.h>
#include <stdint.h>

#define NNODE 50000
#define NEDGE 800000
#define ND    128
#define NH    8
#define DKK   16
#define FFD   512

// ---------------- scratch ----------------
__device__ float g_q [NNODE * ND];
__device__ float g_k [NNODE * ND];
__device__ float g_v [NNODE * ND];
__device__ float g_t1[NNODE * ND];
__device__ float g_x1[NNODE * ND];

// fp16 GEMM operand twins
__device__ __align__(16) __half g_hx [NNODE * ND];    // layer input (rewritten by ff2)
__device__ __align__(16) __half g_hwv[NNODE * ND];    // agg output
__device__ __align__(16) __half g_ht1[NNODE * ND];    // post-LN1
__device__ __align__(16) __half g_hff[NNODE * FFD];   // relu(ff1)
__device__ __align__(16) __half g_hWq[2 * ND * ND];
__device__ __align__(16) __half g_hWk[2 * ND * ND];
__device__ __align__(16) __half g_hWv[2 * ND * ND];
__device__ __align__(16) __half g_hWo[2 * ND * ND];
__device__ __align__(16) __half g_hW1[2 * FFD * ND];
__device__ __align__(16) __half g_hW2[2 * ND * FFD];

// CSR scratch
__device__ int  g_deg[NNODE];
__device__ int  g_off[NNODE + 1];
__device__ int2 g_pe [NEDGE];

// ---------------- helpers ----------------
__device__ __forceinline__ void mma_f16(float* c, const uint32_t* a, const uint32_t* b) {
    asm volatile(
        "mma.sync.aligned.m16n8k16.row.col.f32.f16.f16.f32 "
        "{%0,%1,%2,%3}, {%4,%5,%6,%7}, {%8,%9}, {%0,%1,%2,%3};"
        : "+f"(c[0]), "+f"(c[1]), "+f"(c[2]), "+f"(c[3])
        : "r"(a[0]), "r"(a[1]), "r"(a[2]), "r"(a[3]),
          "r"(b[0]), "r"(b[1]));
}

__device__ __forceinline__ void cp16h(void* dst, const __half* src, bool pred) {
    uint32_t d = (uint32_t)__cvta_generic_to_shared(dst);
    int sz = pred ? 16 : 0;
    asm volatile("cp.async.cg.shared.global [%0], [%1], 16, %2;"
                 :: "r"(d), "l"(src), "r"(sz));
}

// fp32 -> fp16 conversion (4 elems/thread; n % 4 == 0)
__global__ void cvt_kernel(const float* __restrict__ s, __half* __restrict__ d, int n)
{
    int i = (blockIdx.x * blockDim.x + threadIdx.x) * 4;
    if (i >= n) return;
    float4 f = *(const float4*)&s[i];
    *(__half2*)&d[i]     = __floats2half2_rn(f.x, f.y);
    *(__half2*)&d[i + 2] = __floats2half2_rn(f.z, f.w);
}

// ---------------- FP16 GEMM core: C = X @ W^T (+bias)(+res)(relu)(LN) ----------
// C^T = W @ X^T internally; both operands K-contiguous fp16, m16n8k16.
// Block 128m x 128n, KC=64 halves (=128B rows), 3-stage cp.async ring.
// 8 warps: 4 n-warps x 2 m-warps, warp tile 32n x 64m.
// Smem row stride SK=36 uint32 (72 halves) -> conflict-free frag LDS.
#define KC 64
#define SK 36
#define SN 132
#define TILE_U32 (128 * SK)                      // uint32s per operand tile
#define NSTAGE 3
#define GEMM_SMEM_BYTES (NSTAGE * 2 * TILE_U32 * 4)   // 110592; epilogue needs 67584

template<bool RELU, bool LN>
__device__ __forceinline__ void gemm_body(
    const __half* __restrict__ X, const __half* __restrict__ W,
    const float* bias, const float* res,
    const float* gam, const float* bet,
    float* C, __half* Ch, int M, int K, int NOUT, int bm, int bn)
{
    extern __shared__ uint32_t smem[];

    const int tid  = threadIdx.x;
    const int lane = tid & 31;
    const int wid  = tid >> 5;
    const int g    = lane >> 2;
    const int tig  = lane & 3;
    const int wn   = (wid & 3) * 32;
    const int wm   = (wid >> 2) * 64;

    float c[2][8][4];
#pragma unroll
    for (int i = 0; i < 2; i++)
#pragma unroll
        for (int j = 0; j < 8; j++)
#pragma unroll
            for (int t = 0; t < 4; t++) c[i][j][t] = 0.f;

    const int nsteps = K / KC;

    auto prefetch = [&](int s, int b) {
        uint32_t* Wb = smem + b * 2 * TILE_U32;
        uint32_t* Xb = Wb + TILE_U32;
        int k0 = s * KC;
        // each operand: 128 rows x 128B = 1024 x 16B chunks, 4 per thread
#pragma unroll
        for (int i = 0; i < 4; i++) {
            int idx = tid + i * 256;
            int r = idx >> 3, j = idx & 7;
            cp16h((char*)(Wb + r * SK) + j * 16, &W[(long)(bn + r) * K + k0 + j * 8], true);
        }
#pragma unroll
        for (int i = 0; i < 4; i++) {
            int idx = tid + i * 256;
            int r = idx >> 3, j = idx & 7;
            int gm = bm + r;
            cp16h((char*)(Xb + r * SK) + j * 16, &X[(long)gm * K + k0 + j * 8], gm < M);
        }
        asm volatile("cp.async.commit_group;" ::: "memory");
    };

    prefetch(0, 0);
    prefetch(1, 1);

    int buf = 0;
    for (int s = 0; s < nsteps; s++) {
        if (s + 1 < nsteps) asm volatile("cp.async.wait_group 1;" ::: "memory");
        else                asm volatile("cp.async.wait_group 0;" ::: "memory");
        __syncthreads();
        if (s + 2 < nsteps) {
            int nb = buf + 2; if (nb >= NSTAGE) nb -= NSTAGE;
            prefetch(s + 2, nb);
        }

        const uint32_t* Wsu = smem + buf * 2 * TILE_U32;
        const uint32_t* Xsu = Wsu + TILE_U32;

#pragma unroll
        for (int ks = 0; ks < 4; ks++) {         // 4 x k16 per KC=64
            const int kk = ks * 8;               // uint32 units
            uint32_t a[2][4];
#pragma unroll
            for (int tn = 0; tn < 2; tn++) {
                int row = wn + tn * 16 + g;
                a[tn][0] = Wsu[row * SK + kk + tig];
                a[tn][1] = Wsu[(row + 8) * SK + kk + tig];
                a[tn][2] = Wsu[row * SK + kk + tig + 4];
                a[tn][3] = Wsu[(row + 8) * SK + kk + tig + 4];
            }
            uint32_t b[8][2];
#pragma unroll
            for (int tm = 0; tm < 8; tm++) {
                int col = wm + tm * 8 + g;
                b[tm][0] = Xsu[col * SK + kk + tig];
                b[tm][1] = Xsu[col * SK + kk + tig + 4];
            }
#pragma unroll
            for (int tn = 0; tn < 2; tn++)
#pragma unroll
                for (int tm = 0; tm < 8; tm++)
                    mma_f16(c[tn][tm], a[tn], b[tm]);
        }
        if (++buf == NSTAGE) buf = 0;
    }
    __syncthreads();

    // epilogue: transpose through smem
    float* Cs = (float*)smem;
#pragma unroll
    for (int tn = 0; tn < 2; tn++)
#pragma unroll
        for (int tm = 0; tm < 8; tm++) {
            int n = wn + tn * 16 + g;
            int m = wm + tm * 8 + tig * 2;
            Cs[m * SN + n]           = c[tn][tm][0];
            Cs[(m + 1) * SN + n]     = c[tn][tm][1];
            Cs[m * SN + n + 8]       = c[tn][tm][2];
            Cs[(m + 1) * SN + n + 8] = c[tn][tm][3];
        }
    __syncthreads();

#pragma unroll
    for (int i = 0; i < 16; i++) {
        int idx = tid + i * 256;
        int mm = idx >> 5, nq = idx & 31;   // one row per warp per iter, lane == nq
        int gm = bm + mm;
        if (gm >= M) continue;              // warp-uniform
        float4 cv = *(float4*)&Cs[mm * SN + nq * 4];
        if (bias) {
            float4 b4 = *(const float4*)&bias[bn + nq * 4];
            cv.x += b4.x; cv.y += b4.y; cv.z += b4.z; cv.w += b4.w;
        }
        if (res) {
            float4 r4 = *(const float4*)&res[(long)gm * NOUT + bn + nq * 4];
            cv.x += r4.x; cv.y += r4.y; cv.z += r4.z; cv.w += r4.w;
        }
        if (RELU) {
            cv.x = fmaxf(cv.x, 0.f); cv.y = fmaxf(cv.y, 0.f);
            cv.z = fmaxf(cv.z, 0.f); cv.w = fmaxf(cv.w, 0.f);
        }
        if (LN) {
            float s4 = cv.x + cv.y + cv.z + cv.w;
#pragma unroll
            for (int o = 16; o; o >>= 1) s4 += __shfl_xor_sync(0xffffffffu, s4, o);
            float mean = s4 * (1.f / 128.f);
            float dx = cv.x - mean, dy = cv.y - mean, dz = cv.z - mean, dw = cv.w - mean;
            float vv = dx * dx + dy * dy + dz * dz + dw * dw;
#pragma unroll
            for (int o = 16; o; o >>= 1) vv += __shfl_xor_sync(0xffffffffu, vv, o);
            float inv = rsqrtf(vv * (1.f / 128.f) + 1e-5f);
            float4 g4 = *(const float4*)&gam[nq * 4];
            float4 b4 = *(const float4*)&bet[nq * 4];
            cv.x = dx * inv * g4.x + b4.x;
            cv.y = dy * inv * g4.y + b4.y;
            cv.z = dz * inv * g4.z + b4.z;
            cv.w = dw * inv * g4.w + b4.w;
        }
        if (C) *(float4*)&C[(long)gm * NOUT + bn + nq * 4] = cv;
        if (Ch) {
            __half2* hp = (__half2*)&Ch[(long)gm * NOUT + bn + nq * 4];
            hp[0] = __floats2half2_rn(cv.x, cv.y);
            hp[1] = __floats2half2_rn(cv.z, cv.w);
        }
    }
}

template<bool RELU, bool LN>
__global__ __launch_bounds__(256, 2) void gemm_k(
    const __half* __restrict__ X, const __half* __restrict__ W,
    const float* bias, const float* res,
    const float* gam, const float* bet,
    float* C, __half* Ch, int M, int K, int NOUT)
{
    gemm_body<RELU, LN>(X, W, bias, res, gam, bet, C, Ch, M, K, NOUT,
                        blockIdx.x * 128, blockIdx.y * 128);
}

// fused q/k/v: blockIdx.y selects projection
__global__ __launch_bounds__(256, 2) void qkv_k(
    const __half* __restrict__ X,
    const __half* __restrict__ Wq, const __half* __restrict__ Wk,
    const __half* __restrict__ Wv, const float* __restrict__ bq,
    float* __restrict__ q, float* __restrict__ k, float* __restrict__ v, int M)
{
    int w = blockIdx.y;
    const __half* W = (w == 0) ? Wq : (w == 1) ? Wk : Wv;
    const float* bias = (w == 0) ? bq : nullptr;
    float* C = (w == 0) ? q : (w == 1) ? k : v;
    gemm_body<false, false>(X, W, bias, nullptr, nullptr, nullptr, C, nullptr,
                            M, ND, ND, blockIdx.x * 128, 0);
}

// ================= CSR build =================
__global__ void hist_kernel(const int* __restrict__ dst)
{
    int e = blockIdx.x * blockDim.x + threadIdx.x;
    if (e < NEDGE) atomicAdd(&g_deg[dst[e]], 1);
}

__global__ void scan_kernel()
{
    __shared__ int sh[1024];
    __shared__ int carry;
    int t = threadIdx.x;
    if (t == 0) { carry = 0; g_off[0] = 0; }
    __syncthreads();
    for (int base = 0; base < NNODE; base += 1024) {
        int i = base + t;
        int val = (i < NNODE) ? g_deg[i] : 0;
        sh[t] = val;
        __syncthreads();
#pragma unroll
        for (int o = 1; o < 1024; o <<= 1) {
            int add = (t >= o) ? sh[t - o] : 0;
            __syncthreads();
            sh[t] += add;
            __syncthreads();
        }
        int inc = sh[t] + carry;
        if (i < NNODE) g_off[i + 1] = inc;
        __syncthreads();
        if (t == 1023) carry = inc;
        __syncthreads();
    }
}

__global__ void scatter_kernel(const int* __restrict__ src,
                               const int* __restrict__ dst,
                               const int* __restrict__ edges)
{
    int e = blockIdx.x * blockDim.x + threadIdx.x;
    if (e >= NEDGE) return;
    int d = dst[e];
    int idx = atomicAdd(&g_deg[d], -1) - 1;
    g_pe[g_off[d] + idx] = make_int2(src[e], edges[e]);
}

// ================= per-dst aggregation (one warp per node, 2-wide) =================
__global__ __launch_bounds__(256) void agg_kernel(const float* __restrict__ rel)
{
    int node = (blockIdx.x * blockDim.x + threadIdx.x) >> 5;
    int lane = threadIdx.x & 31;
    if (node >= NNODE) return;

    const int beg = g_off[node];
    const int end = g_off[node + 1];

    const float4 q4 = *(const float4*)&g_q[(long)node * ND + lane * 4];
    float4 acc = make_float4(0.f, 0.f, 0.f, 0.f);
    float zacc = 0.f;

    int i = beg;
    for (; i + 2 <= end; i += 2) {
        int2 p0 = g_pe[i];
        int2 p1 = g_pe[i + 1];
        const float4 e0 = *(const float4*)&rel[(long)p0.y * DKK + (lane & 3) * 4];
        const float4 e1 = *(const float4*)&rel[(long)p1.y * DKK + (lane & 3) * 4];
        const float4 k0 = *(const float4*)&g_k[(long)p0.x * ND + lane * 4];
        const float4 k1 = *(const float4*)&g_k[(long)p1.x * ND + lane * 4];
        const float4 v0 = *(const float4*)&g_v[(long)p0.x * ND + lane * 4];
        const float4 v1 = *(const float4*)&g_v[(long)p1.x * ND + lane * 4];

        float s0 = (k0.x + e0.x) * q4.x + (k0.y + e0.y) * q4.y +
                   (k0.z + e0.z) * q4.z + (k0.w + e0.w) * q4.w;
        float s1 = (k1.x + e1.x) * q4.x + (k1.y + e1.y) * q4.y +
                   (k1.z + e1.z) * q4.z + (k1.w + e1.w) * q4.w;
        s0 += __shfl_xor_sync(0xffffffffu, s0, 1);
        s1 += __shfl_xor_sync(0xffffffffu, s1, 1);
        s0 += __shfl_xor_sync(0xffffffffu, s0, 2);
        s1 += __shfl_xor_sync(0xffffffffu, s1, 2);

        float sc0 = __expf(fminf(fmaxf(s0 * 0.25f, -5.f), 5.f));
        float sc1 = __expf(fminf(fmaxf(s1 * 0.25f, -5.f), 5.f));

        acc.x += (v0.x + e0.x) * sc0 + (v1.x + e1.x) * sc1;
        acc.y += (v0.y + e0.y) * sc0 + (v1.y + e1.y) * sc1;
        acc.z += (v0.z + e0.z) * sc0 + (v1.z + e1.z) * sc1;
        acc.w += (v0.w + e0.w) * sc0 + (v1.w + e1.w) * sc1;
        zacc  += sc0 + sc1;
    }
    if (i < end) {
        int2 p0 = g_pe[i];
        const float4 e0 = *(const float4*)&rel[(long)p0.y * DKK + (lane & 3) * 4];
        const float4 k0 = *(const float4*)&g_k[(long)p0.x * ND + lane * 4];
        const float4 v0 = *(const float4*)&g_v[(long)p0.x * ND + lane * 4];
        float s0 = (k0.x + e0.x) * q4.x + (k0.y + e0.y) * q4.y +
                   (k0.z + e0.z) * q4.z + (k0.w + e0.w) * q4.w;
        s0 += __shfl_xor_sync(0xffffffffu, s0, 1);
        s0 += __shfl_xor_sync(0xffffffffu, s0, 2);
        float sc0 = __expf(fminf(fmaxf(s0 * 0.25f, -5.f), 5.f));
        acc.x += (v0.x + e0.x) * sc0;
        acc.y += (v0.y + e0.y) * sc0;
        acc.z += (v0.z + e0.z) * sc0;
        acc.w += (v0.w + e0.w) * sc0;
        zacc  += sc0;
    }

    float inv = 1.f / zacc;
    // write fp16 twin only (o-proj GEMM is the sole consumer)
    __half2* hp = (__half2*)&g_hwv[(long)node * ND + lane * 4];
    hp[0] = __floats2half2_rn(acc.x * inv, acc.y * inv);
    hp[1] = __floats2half2_rn(acc.z * inv, acc.w * inv);
}

// ---------------- host driver ----------------
extern "C" void kernel_launch(void* const* d_in, const int* in_sizes, int n_in,
                              void* d_out, int out_size)
{
    const float* x     = (const float*)d_in[0];
    const int*   edges = (const int*)  d_in[1];
    const int*   src   = (const int*)  d_in[2];
    const int*   dst   = (const int*)  d_in[3];
    const float* rel   = (const float*)d_in[4];
    const float* Wq    = (const float*)d_in[5];
    const float* bq    = (const float*)d_in[6];
    const float* Wk    = (const float*)d_in[7];
    const float* Wv    = (const float*)d_in[8];
    const float* Wo    = (const float*)d_in[9];
    const float* bo    = (const float*)d_in[10];
    const float* ln1g  = (const float*)d_in[11];
    const float* ln1b  = (const float*)d_in[12];
    const float* W1    = (const float*)d_in[13];
    const float* b1    = (const float*)d_in[14];
    const float* W2    = (const float*)d_in[15];
    const float* b2    = (const float*)d_in[16];
    const float* ln2g  = (const float*)d_in[17];
    const float* ln2b  = (const float*)d_in[18];

    const int M = NNODE;
    const int E = NEDGE;

    float *q, *k, *v, *t1, *x1;
    __half *hx, *hwv, *ht1, *hff, *hWq, *hWk, *hWv, *hWo, *hW1, *hW2;
    int* degp;
    cudaGetSymbolAddress((void**)&q,   g_q);
    cudaGetSymbolAddress((void**)&k,   g_k);
    cudaGetSymbolAddress((void**)&v,   g_v);
    cudaGetSymbolAddress((void**)&t1,  g_t1);
    cudaGetSymbolAddress((void**)&x1,  g_x1);
    cudaGetSymbolAddress((void**)&hx,  g_hx);
    cudaGetSymbolAddress((void**)&hwv, g_hwv);
    cudaGetSymbolAddress((void**)&ht1, g_ht1);
    cudaGetSymbolAddress((void**)&hff, g_hff);
    cudaGetSymbolAddress((void**)&hWq, g_hWq);
    cudaGetSymbolAddress((void**)&hWk, g_hWk);
    cudaGetSymbolAddress((void**)&hWv, g_hWv);
    cudaGetSymbolAddress((void**)&hWo, g_hWo);
    cudaGetSymbolAddress((void**)&hW1, g_hW1);
    cudaGetSymbolAddress((void**)&hW2, g_hW2);
    cudaGetSymbolAddress((void**)&degp, g_deg);

    cudaFuncSetAttribute(gemm_k<false, true>,
        cudaFuncAttributeMaxDynamicSharedMemorySize, GEMM_SMEM_BYTES);
    cudaFuncSetAttribute(gemm_k<true, false>,
        cudaFuncAttributeMaxDynamicSharedMemorySize, GEMM_SMEM_BYTES);
    cudaFuncSetAttribute(qkv_k,
        cudaFuncAttributeMaxDynamicSharedMemorySize, GEMM_SMEM_BYTES);

    const int MB = (M + 127) / 128;
    dim3 gQKV(MB, 3);
    dim3 gP(MB, 1);
    dim3 gF1(MB, FFD / 128);
    int eBlocks   = (E + 255) / 256;
    int aggBlocks = (M * 32 + 255) / 256;

    auto cvtLaunch = [](const float* s, __half* d, int n) {
        cvt_kernel<<<(n / 4 + 255) / 256, 256>>>(s, d, n);
    };

    // ---- one-time conversions (call-constant inputs) ----
    cvtLaunch(x,  hx,  M * ND);
    cvtLaunch(Wq, hWq, 2 * ND * ND);
    cvtLaunch(Wk, hWk, 2 * ND * ND);
    cvtLaunch(Wv, hWv, 2 * ND * ND);
    cvtLaunch(Wo, hWo, 2 * ND * ND);
    cvtLaunch(W1, hW1, 2 * FFD * ND);
    cvtLaunch(W2, hW2, 2 * ND * FFD);

    // ---- CSR build ----
    cudaMemsetAsync(degp, 0, NNODE * sizeof(int));
    hist_kernel<<<eBlocks, 256>>>(dst);
    scan_kernel<<<1, 1024>>>();
    scatter_kernel<<<eBlocks, 256>>>(src, dst, edges);

    const float* xin = x;     // fp32 residual source
    for (int li = 0; li < 2; li++) {
        float* xout = (li == 0) ? x1 : (float*)d_out;
        const __half* wWq = hWq + (long)li * ND * ND;
        const __half* wWk = hWk + (long)li * ND * ND;
        const __half* wWv = hWv + (long)li * ND * ND;
        const __half* wWo = hWo + (long)li * ND * ND;
        const __half* wW1 = hW1 + (long)li * FFD * ND;
        const __half* wW2 = hW2 + (long)li * ND * FFD;

        // q/k/v projections (input: hx)
        qkv_k<<<gQKV, 256, GEMM_SMEM_BYTES>>>(hx, wWq, wWk, wWv, bq + li * ND, q, k, v, M);

        // attention aggregation -> hwv (fp16)
        agg_kernel<<<aggBlocks, 256>>>(rel);

        // o-proj + residual + LN1 -> t1 (fp32) + ht1 (fp16)
        gemm_k<false, true><<<gP, 256, GEMM_SMEM_BYTES>>>(
            hwv, wWo, bo + li * ND, xin, ln1g + li * ND, ln1b + li * ND,
            t1, ht1, M, ND, ND);

        // FF1: relu(ht1 @ W1^T + b1) -> hff (fp16 only)
        gemm_k<true, false><<<gF1, 256, GEMM_SMEM_BYTES>>>(
            ht1, wW1, b1 + li * FFD, nullptr, nullptr, nullptr,
            nullptr, hff, M, ND, FFD);

        // FF2 + residual(t1) + LN2 -> xout (fp32) + hx (fp16, next layer input)
        gemm_k<false, true><<<gP, 256, GEMM_SMEM_BYTES>>>(
            hff, wW2, b2 + li * ND, t1, ln2g + li * ND, ln2b + li * ND,
            xout, hx, M, FFD, ND);

        xin = xout;
    }
}